// round 10
// baseline (speedup 1.0000x reference)
#include <cuda_runtime.h>
#include <cstdint>

#define T_SEQ 512
#define H 32
#define GSTEP 16   // x tile depth (steps per prefetch group)

typedef unsigned long long u64;

__device__ __forceinline__ u64 fma2(u64 a, u64 b, u64 c) {
    u64 d;
    asm("fma.rn.f32x2 %0, %1, %2, %3;" : "=l"(d) : "l"(a), "l"(b), "l"(c));
    return d;
}
__device__ __forceinline__ u64 pack2(float lo, float hi) {
    u64 d;
    asm("mov.b64 %0, {%1, %2};" : "=l"(d) : "f"(lo), "f"(hi));
    return d;
}
__device__ __forceinline__ float lo_hi_sum(u64 a) {
    unsigned lo, hi;
    asm("mov.b64 {%0,%1}, %2;" : "=r"(lo), "=r"(hi) : "l"(a));
    return __uint_as_float(lo) + __uint_as_float(hi);
}
__device__ __forceinline__ float tanh_mufu(float x) {
    float y;
    asm("tanh.approx.f32 %0, %1;" : "=f"(y) : "f"(x));
    return y;
}

// ============================================================================
// Fused kernel: per-warp 2-layer RNN over one sequence, xin computed INLINE.
// Half-j split: lane L reads j-half jh=L>>4 of x_t, h1, h2; owns unit rows
// u0=L&15 and u0+16. Layer-1 input projection accumulates into the SAME
// chains as W_hh1*h1, so the single cross-half exchange covers everything.
//   h1_{k+1} = tanh(b1 + W_ih1 x_{k+1} + W_hh1 h1_k)
//   h2_k     = tanh(b2 + W_ih2 h1_k   + W_hh2 h2_{k-1})
// x staged GSTEP steps ahead in a double-buffered smem tile (coalesced LDG).
// ============================================================================
__global__ __launch_bounds__(32, 12)
void rnn_fused_kernel(const float* __restrict__ x,
                      const float* __restrict__ W_ih1,
                      const float* __restrict__ W_hh1,
                      const float* __restrict__ b_ih1,
                      const float* __restrict__ b_hh1,
                      const float* __restrict__ W_ih2,
                      const float* __restrict__ W_hh2,
                      const float* __restrict__ b_ih2,
                      const float* __restrict__ b_hh2,
                      const float* __restrict__ W_fc,
                      const float* __restrict__ b_fc,
                      float* __restrict__ out, int Bn)
{
    const int lane = threadIdx.x & 31;
    const int jh   = lane >> 4;        // j-half this lane reads
    const int u0   = lane & 15;        // unit pair (u0, u0+16)
    const int b    = blockIdx.x;
    if (b >= Bn) return;

    __shared__ __align__(16) float s[2][2 * H];        // h ping-pong [buf][h1|h2]
    __shared__ __align__(16) float sx[2][GSTEP][32];   // x tile [buf][d][i]

    // per-lane weight half-rows: rows u0, u0+16; cols [16*jh, 16*jh+16)
    u64 wi1_0[8], wi1_1[8], w1_0[8], w1_1[8], w2_0[8], w2_1[8], w3_0[8], w3_1[8];
    {
        const int off = jh * 16;
        const u64* p;
        p = (const u64*)(W_ih1 + u0 * H + off);
        #pragma unroll
        for (int k = 0; k < 8; k++) wi1_0[k] = p[k];
        p = (const u64*)(W_ih1 + (u0 + 16) * H + off);
        #pragma unroll
        for (int k = 0; k < 8; k++) wi1_1[k] = p[k];
        p = (const u64*)(W_hh1 + u0 * H + off);
        #pragma unroll
        for (int k = 0; k < 8; k++) w1_0[k] = p[k];
        p = (const u64*)(W_hh1 + (u0 + 16) * H + off);
        #pragma unroll
        for (int k = 0; k < 8; k++) w1_1[k] = p[k];
        p = (const u64*)(W_ih2 + u0 * H + off);
        #pragma unroll
        for (int k = 0; k < 8; k++) w2_0[k] = p[k];
        p = (const u64*)(W_ih2 + (u0 + 16) * H + off);
        #pragma unroll
        for (int k = 0; k < 8; k++) w2_1[k] = p[k];
        p = (const u64*)(W_hh2 + u0 * H + off);
        #pragma unroll
        for (int k = 0; k < 8; k++) w3_0[k] = p[k];
        p = (const u64*)(W_hh2 + (u0 + 16) * H + off);
        #pragma unroll
        for (int k = 0; k < 8; k++) w3_1[k] = p[k];
    }
    // biases folded into chain inits (jh==0 lanes only, so the cross-half
    // combine counts each bias exactly once)
    const u64 b1i0 = (jh == 0) ? pack2(b_ih1[u0]      + b_hh1[u0],      0.0f) : 0ull;
    const u64 b1i1 = (jh == 0) ? pack2(b_ih1[u0 + 16] + b_hh1[u0 + 16], 0.0f) : 0ull;
    const u64 b2i0 = (jh == 0) ? pack2(b_ih2[u0]      + b_hh2[u0],      0.0f) : 0ull;
    const u64 b2i1 = (jh == 0) ? pack2(b_ih2[u0 + 16] + b_hh2[u0 + 16], 0.0f) : 0ull;

    const float* xb = x + (size_t)b * T_SEQ * H;

    // ---- prologue: h1_0 = tanh(b1 + W_ih1 x_0), h2_{-1} = 0 ----
    sx[1][0][lane] = xb[lane];          // stage x_0 (temp slot, reclaimed later)
    __syncwarp();
    {
        const ulonglong2* xv = (const ulonglong2*)&sx[1][0][jh * 16];
        u64 a0 = b1i0, a1 = b1i1;
        #pragma unroll
        for (int m = 0; m < 4; m++) {
            ulonglong2 v = xv[m];
            a0 = fma2(v.x, wi1_0[2 * m],     a0);
            a0 = fma2(v.y, wi1_0[2 * m + 1], a0);
            a1 = fma2(v.x, wi1_1[2 * m],     a1);
            a1 = fma2(v.y, wi1_1[2 * m + 1], a1);
        }
        float sa0 = lo_hi_sum(a0), sa1 = lo_hi_sum(a1);
        float send = jh ? sa0 : sa1;
        float recv = __shfl_xor_sync(0xFFFFFFFFu, send, 16);
        float keep = jh ? sa1 : sa0;
        s[1][lane]     = tanh_mufu(keep + recv);   // h1_0
        s[1][H + lane] = 0.0f;                     // h2_{-1}
    }
    __syncwarp();

    // preload x tile group 0: t = 1..16
    #pragma unroll
    for (int d = 0; d < GSTEP; d++)
        sx[0][d][lane] = xb[(size_t)(d + 1) * H + lane];

    float h2A = 0.0f;

    for (int g = 0; g < T_SEQ / GSTEP; ++g) {
        const int buf = g & 1;

        // burst-prefetch next tile: t = g*16+17 .. g*16+32, clamped to T-1
        {
            const int tb = g * GSTEP + GSTEP + 1;
            #pragma unroll
            for (int d = 0; d < GSTEP; d++) {
                int t = tb + d; if (t > T_SEQ - 1) t = T_SEQ - 1;
                sx[buf ^ 1][d][lane] = xb[(size_t)t * H + lane];
            }
        }

        #pragma unroll 2
        for (int kk = 0; kk < GSTEP; ++kk) {
            const int p = kk & 1;   // g*16 even -> parity of k == parity of kk
            const float* sq = &s[p ^ 1][jh * 16];
            const ulonglong2* h1v = (const ulonglong2*)(sq);
            const ulonglong2* h2v = (const ulonglong2*)(sq + H);
            const ulonglong2* xv  = (const ulonglong2*)&sx[buf][kk][jh * 16];

            u64 a0 = b1i0, a1 = b1i1;   // layer-1 chains (xin + recurrence)
            u64 c0 = b2i0, c1 = b2i1;   // layer-2 chains

            #pragma unroll
            for (int m = 0; m < 4; m++) {
                ulonglong2 v = xv[m];   // x_{k+1} half
                a0 = fma2(v.x, wi1_0[2 * m],     a0);
                a0 = fma2(v.y, wi1_0[2 * m + 1], a0);
                a1 = fma2(v.x, wi1_1[2 * m],     a1);
                a1 = fma2(v.y, wi1_1[2 * m + 1], a1);
            }
            #pragma unroll
            for (int m = 0; m < 4; m++) {
                ulonglong2 v = h1v[m];  // h1_k half
                a0 = fma2(v.x, w1_0[2 * m],     a0);
                a0 = fma2(v.y, w1_0[2 * m + 1], a0);
                a1 = fma2(v.x, w1_1[2 * m],     a1);
                a1 = fma2(v.y, w1_1[2 * m + 1], a1);
                c0 = fma2(v.x, w2_0[2 * m],     c0);
                c0 = fma2(v.y, w2_0[2 * m + 1], c0);
                c1 = fma2(v.x, w2_1[2 * m],     c1);
                c1 = fma2(v.y, w2_1[2 * m + 1], c1);
            }
            #pragma unroll
            for (int m = 0; m < 4; m++) {
                ulonglong2 v = h2v[m];  // h2_{k-1} half
                c0 = fma2(v.x, w3_0[2 * m],     c0);
                c0 = fma2(v.y, w3_0[2 * m + 1], c0);
                c1 = fma2(v.x, w3_1[2 * m],     c1);
                c1 = fma2(v.y, w3_1[2 * m + 1], c1);
            }

            float sa0 = lo_hi_sum(a0), sa1 = lo_hi_sum(a1);
            float sc0 = lo_hi_sum(c0), sc1 = lo_hi_sum(c1);

            // directed half exchange: 1 shfl + 1 add per output
            float sendA = jh ? sa0 : sa1;
            float sendC = jh ? sc0 : sc1;
            float recvA = __shfl_xor_sync(0xFFFFFFFFu, sendA, 16);
            float recvC = __shfl_xor_sync(0xFFFFFFFFu, sendC, 16);
            float keepA = jh ? sa1 : sa0;
            float keepC = jh ? sc1 : sc0;

            const float h1n = tanh_mufu(keepA + recvA);   // h1_{k+1}
            const float h2n = tanh_mufu(keepC + recvC);   // h2_k

            s[p][lane]     = h1n;
            s[p][H + lane] = h2n;
            __syncwarp();

            h2A = h2n;
        }
    }

    // out[b] = h2_{T-1} . W_fc + b_fc
    float v = h2A * W_fc[lane];
    #pragma unroll
    for (int o = 16; o; o >>= 1) v += __shfl_xor_sync(0xFFFFFFFFu, v, o);
    if (lane == 0) out[b] = v + b_fc[0];
}

extern "C" void kernel_launch(void* const* d_in, const int* in_sizes, int n_in,
                              void* d_out, int out_size)
{
    const float* x     = (const float*)d_in[0];
    const float* W_ih1 = (const float*)d_in[1];
    const float* W_hh1 = (const float*)d_in[2];
    const float* b_ih1 = (const float*)d_in[3];
    const float* b_hh1 = (const float*)d_in[4];
    const float* W_ih2 = (const float*)d_in[5];
    const float* W_hh2 = (const float*)d_in[6];
    const float* b_ih2 = (const float*)d_in[7];
    const float* b_hh2 = (const float*)d_in[8];
    const float* W_fc  = (const float*)d_in[9];
    const float* b_fc  = (const float*)d_in[10];
    float* out = (float*)d_out;

    const int Bn = in_sizes[0] / (T_SEQ * H);

    rnn_fused_kernel<<<Bn, 32>>>(x, W_ih1, W_hh1, b_ih1, b_hh1,
                                 W_ih2, W_hh2, b_ih2, b_hh2,
                                 W_fc, b_fc, out, Bn);
}